// round 12
// baseline (speedup 1.0000x reference)
#include <cuda_runtime.h>
#include <cstdint>

// ---------------------------------------------------------------------------
// GCN layer, padded-bucket CSR:
//   1. slot[d*CAP + cursor[d]++] = s   (fill; cursors arrive zeroed)
//   2. agg[n] = sum_j x[slot[n*CAP+j]]; cursor[n] = 0   (gather + reset)
//   3. out = relu(agg @ W^T) + x   (smem GEMM, vectorized bounce epilogue)
// Cursors are zero at module load and re-zeroed by every gather -> no zero
// kernel needed; invariant holds across correctness run / capture / replays.
// ---------------------------------------------------------------------------

#define D 64
#define D4 (D / 4)
#define D2 (D / 2)
#define MAX_NODES 50000
#define CAP 96
#define TILE_NODES 64
#define APAD 68   // row stride (floats): 272B, 16B-aligned; banks shift 4/row

// __device__ scratch (allocations forbidden; zero-initialized at load)
__device__ int    g_cursor[MAX_NODES];
__device__ int    g_slot[MAX_NODES * CAP];      // 19.2 MB
__device__ float4 g_agg[MAX_NODES * D4];        // 12.8 MB

// ---------------------------------------------------------------------------
// 1. fill buckets (4 edges per thread via int4 loads)
// ---------------------------------------------------------------------------
__global__ void fill_kernel(const int4* __restrict__ src4,
                            const int4* __restrict__ dst4,
                            const int* __restrict__ src,
                            const int* __restrict__ dst,
                            int n_edges) {
    int t = blockIdx.x * blockDim.x + threadIdx.x;
    int n4 = n_edges >> 2;
    if (t < n4) {
        int4 s = src4[t];
        int4 d = dst4[t];
        int p0 = atomicAdd(&g_cursor[d.x], 1);
        int p1 = atomicAdd(&g_cursor[d.y], 1);
        int p2 = atomicAdd(&g_cursor[d.z], 1);
        int p3 = atomicAdd(&g_cursor[d.w], 1);
        if (p0 < CAP) g_slot[d.x * CAP + p0] = s.x;
        if (p1 < CAP) g_slot[d.y * CAP + p1] = s.y;
        if (p2 < CAP) g_slot[d.z * CAP + p2] = s.z;
        if (p3 < CAP) g_slot[d.w * CAP + p3] = s.w;
    }
    if (t < (n_edges & 3)) {
        int e = (n4 << 2) + t;
        int d = dst[e];
        int p = atomicAdd(&g_cursor[d], 1);
        if (p < CAP) g_slot[d * CAP + p] = src[e];
    }
}

// ---------------------------------------------------------------------------
// 2. gather + cursor reset: 16 threads (half-warp) per node. Indices loaded
//    coalesced then shuffle-broadcast; x rows read as coalesced 256B.
//    Lane 0 zeroes the cursor for the next launch (self-cleaning).
// ---------------------------------------------------------------------------
__global__ void gather_kernel(const float4* __restrict__ x4, int n_nodes) {
    int gid  = blockIdx.x * blockDim.x + threadIdx.x;
    int node = gid >> 4;
    int lane = gid & 15;
    if (node >= n_nodes) return;

    int cnt = g_cursor[node];
    if (lane == 0) g_cursor[node] = 0;     // reset for next launch
    if (cnt > CAP) cnt = CAP;

    const int* slots = &g_slot[node * CAP];
    unsigned mask = (threadIdx.x & 16) ? 0xFFFF0000u : 0x0000FFFFu;

    float4 acc = make_float4(0.f, 0.f, 0.f, 0.f);

    for (int base = 0; base < cnt; base += 16) {
        int idx = slots[base + lane];
#pragma unroll
        for (int j = 0; j < 16; j++) {
            int s = __shfl_sync(mask, idx, j, 16);
            if (base + j < cnt) {
                float4 v = x4[(long)s * D4 + lane];
                acc.x += v.x; acc.y += v.y; acc.z += v.z; acc.w += v.w;
            }
        }
    }
    g_agg[(long)node * D4 + lane] = acc;
}

// ---------------------------------------------------------------------------
// 3. smem GEMM + ReLU + residual, vectorized bounce epilogue.
//    Block: 128 threads, 64 nodes. Thread (tn = t>>3, to = t&7):
//      nodes {tn + 16i : i<4} x outputs {to + 8j : j<8}, k-step 2 (float2).
//    After the k-loop, h is written back into As (STS, <=2-way conflict),
//    then a second pass does fully-coalesced float4 LDS + LDG(x) + STG(out).
// ---------------------------------------------------------------------------
__global__ void __launch_bounds__(128, 6)
gemm_relu_res_kernel(const float* __restrict__ W,
                     const float4* __restrict__ x4,
                     float4* __restrict__ out4,
                     int n_nodes) {
    __shared__ float2 Wt2[D2 * D];             // Wt2[k2*64 + o] (16 KB)
    __shared__ float  As[TILE_NODES * APAD];   // agg tile / h tile (17.4 KB)

    // stage W transposed as float2: Wt2[k2][o]
    {
        const float2* W2 = (const float2*)W;   // W2[o*32 + k2], coalesced
        for (int i = threadIdx.x; i < D * D2; i += blockDim.x) {
            int o  = i >> 5;
            int k2 = i & 31;
            Wt2[k2 * D + o] = W2[i];
        }
    }

    int base = blockIdx.x * TILE_NODES;

    // cooperative coalesced load of agg tile: 1024 float4, 128 threads -> 8 ea
    {
        const float4* ag = &g_agg[(long)base * D4];
        int lim = (n_nodes - base) * D4;
        if (lim > TILE_NODES * D4) lim = TILE_NODES * D4;
        for (int i = threadIdx.x; i < TILE_NODES * D4; i += blockDim.x) {
            float4 v = (i < lim) ? ag[i] : make_float4(0.f, 0.f, 0.f, 0.f);
            int row = i >> 4;
            int k4  = i & 15;
            *(float4*)&As[row * APAD + k4 * 4] = v;
        }
    }
    __syncthreads();

    int t  = threadIdx.x;
    int to = t & 7;
    int tn = t >> 3;       // 0..15

    float acc[4][8];
#pragma unroll
    for (int i = 0; i < 4; i++)
#pragma unroll
        for (int j = 0; j < 8; j++) acc[i][j] = 0.f;

#pragma unroll 4
    for (int k2 = 0; k2 < D2; k2++) {
        float2 a[4];
#pragma unroll
        for (int i = 0; i < 4; i++)
            a[i] = *(const float2*)&As[(tn + 16 * i) * APAD + k2 * 2];

        float2 w[8];
#pragma unroll
        for (int j = 0; j < 8; j++) w[j] = Wt2[k2 * D + to + 8 * j];

#pragma unroll
        for (int i = 0; i < 4; i++) {
#pragma unroll
            for (int j = 0; j < 8; j++) {
                acc[i][j] = fmaf(a[i].x, w[j].x, acc[i][j]);
                acc[i][j] = fmaf(a[i].y, w[j].y, acc[i][j]);
            }
        }
    }

    // bounce h through As (all reads of As for GEMM are done)
    __syncthreads();
#pragma unroll
    for (int i = 0; i < 4; i++) {
        int row = tn + 16 * i;
#pragma unroll
        for (int j = 0; j < 8; j++) {
            As[row * APAD + to + 8 * j] = acc[i][j];
        }
    }
    __syncthreads();

    // vectorized epilogue: coalesced float4 LDS + x-LDG + out-STG
    {
        int lim = (n_nodes - base) * D4;
        if (lim > TILE_NODES * D4) lim = TILE_NODES * D4;
        for (int i = threadIdx.x; i < TILE_NODES * D4; i += blockDim.x) {
            if (i < lim) {
                int row = i >> 4;
                int k4  = i & 15;
                float4 h  = *(const float4*)&As[row * APAD + k4 * 4];
                float4 xr = x4[(long)base * D4 + i];
                float4 r;
                r.x = fmaxf(h.x, 0.f) + xr.x;
                r.y = fmaxf(h.y, 0.f) + xr.y;
                r.z = fmaxf(h.z, 0.f) + xr.z;
                r.w = fmaxf(h.w, 0.f) + xr.w;
                out4[(long)base * D4 + i] = r;
            }
        }
    }
}

// ---------------------------------------------------------------------------
// Launch
// ---------------------------------------------------------------------------
extern "C" void kernel_launch(void* const* d_in, const int* in_sizes, int n_in,
                              void* d_out, int out_size) {
    const float* x   = (const float*)d_in[0];
    const float* W   = (const float*)d_in[1];
    const int*   src = (const int*)d_in[2];
    const int*   dst = (const int*)d_in[3];
    float*       out = (float*)d_out;

    int n_nodes = in_sizes[0] / D;
    int n_edges = in_sizes[2];

    const float4* x4   = (const float4*)x;
    float4*       out4 = (float4*)out;
    const int4*   src4 = (const int4*)src;
    const int4*   dst4 = (const int4*)dst;

    // 1) fill buckets (cursors arrive zeroed: load-time init / prior gather)
    {
        int work = (n_edges >> 2) + 4;
        int threads = 256;
        int blocks = (work + threads - 1) / threads;
        fill_kernel<<<blocks, threads>>>(src4, dst4, src, dst, n_edges);
    }
    // 2) gather + cursor reset
    {
        long total = (long)n_nodes * 16;
        int threads = 256;
        int blocks = (int)((total + threads - 1) / threads);
        gather_kernel<<<blocks, threads>>>(x4, n_nodes);
    }
    // 3) smem GEMM + ReLU + residual
    {
        int blocks = (n_nodes + TILE_NODES - 1) / TILE_NODES;
        gemm_relu_res_kernel<<<blocks, 128>>>(W, x4, out4, n_nodes);
    }
}

// round 13
// speedup vs baseline: 1.0106x; 1.0106x over previous
#include <cuda_runtime.h>
#include <cstdint>

// ---------------------------------------------------------------------------
// GCN layer, padded-bucket CSR, self-cleaning cursors:
//   1. slot[d*CAP + cursor[d]++] = s     (fill; cursors arrive zeroed)
//   2. agg[n] = sum_j x[slot[n*CAP+j]]; cursor[n] = 0   (gather + reset)
//   3. out = relu(agg @ W^T) + x   (smem GEMM with packed fma.rn.f32x2:
//      lo/hi halves accumulate even/odd-k partial sums)
// Cursors are zero at module load and re-zeroed by every gather -> invariant
// holds across correctness run / capture / replays (no zero kernel).
// ---------------------------------------------------------------------------

#define D 64
#define D4 (D / 4)
#define D2 (D / 2)
#define MAX_NODES 50000
#define CAP 96
#define TILE_NODES 64
#define APAD 68   // row stride (floats): 272B, 16B-aligned; banks shift 4/row

// __device__ scratch (allocations forbidden; zero-initialized at load)
__device__ int    g_cursor[MAX_NODES];
__device__ int    g_slot[MAX_NODES * CAP];      // 19.2 MB
__device__ float4 g_agg[MAX_NODES * D4];        // 12.8 MB

// packed dual FMA: {d.lo,d.hi} = {a.lo*b.lo+c.lo, a.hi*b.hi+c.hi}
__device__ __forceinline__ unsigned long long
ffma2(unsigned long long a, unsigned long long b, unsigned long long c) {
    unsigned long long d;
    asm("fma.rn.f32x2 %0, %1, %2, %3;" : "=l"(d) : "l"(a), "l"(b), "l"(c));
    return d;
}

// ---------------------------------------------------------------------------
// 1. fill buckets (4 edges per thread via int4 loads)
// ---------------------------------------------------------------------------
__global__ void fill_kernel(const int4* __restrict__ src4,
                            const int4* __restrict__ dst4,
                            const int* __restrict__ src,
                            const int* __restrict__ dst,
                            int n_edges) {
    int t = blockIdx.x * blockDim.x + threadIdx.x;
    int n4 = n_edges >> 2;
    if (t < n4) {
        int4 s = src4[t];
        int4 d = dst4[t];
        int p0 = atomicAdd(&g_cursor[d.x], 1);
        int p1 = atomicAdd(&g_cursor[d.y], 1);
        int p2 = atomicAdd(&g_cursor[d.z], 1);
        int p3 = atomicAdd(&g_cursor[d.w], 1);
        if (p0 < CAP) g_slot[d.x * CAP + p0] = s.x;
        if (p1 < CAP) g_slot[d.y * CAP + p1] = s.y;
        if (p2 < CAP) g_slot[d.z * CAP + p2] = s.z;
        if (p3 < CAP) g_slot[d.w * CAP + p3] = s.w;
    }
    if (t < (n_edges & 3)) {
        int e = (n4 << 2) + t;
        int d = dst[e];
        int p = atomicAdd(&g_cursor[d], 1);
        if (p < CAP) g_slot[d * CAP + p] = src[e];
    }
}

// ---------------------------------------------------------------------------
// 2. gather + cursor reset: 16 threads (half-warp) per node. Indices loaded
//    coalesced then shuffle-broadcast; x rows read as coalesced 256B.
// ---------------------------------------------------------------------------
__global__ void gather_kernel(const float4* __restrict__ x4, int n_nodes) {
    int gid  = blockIdx.x * blockDim.x + threadIdx.x;
    int node = gid >> 4;
    int lane = gid & 15;
    if (node >= n_nodes) return;

    int cnt = g_cursor[node];
    if (lane == 0) g_cursor[node] = 0;     // reset for next launch
    if (cnt > CAP) cnt = CAP;

    const int* slots = &g_slot[node * CAP];
    unsigned mask = (threadIdx.x & 16) ? 0xFFFF0000u : 0x0000FFFFu;

    float4 acc = make_float4(0.f, 0.f, 0.f, 0.f);

    for (int base = 0; base < cnt; base += 16) {
        int idx = slots[base + lane];
#pragma unroll
        for (int j = 0; j < 16; j++) {
            int s = __shfl_sync(mask, idx, j, 16);
            if (base + j < cnt) {
                float4 v = x4[(long)s * D4 + lane];
                acc.x += v.x; acc.y += v.y; acc.z += v.z; acc.w += v.w;
            }
        }
    }
    g_agg[(long)node * D4 + lane] = acc;
}

// ---------------------------------------------------------------------------
// 3. smem GEMM + ReLU + residual with packed FFMA2.
//    Block: 128 threads, 64 nodes. Thread (tn = t>>3 in 0..15, to = t&7):
//      nodes {tn + 16i : i<4} x outputs {to + 8j : j<8}.
//    Per k2-step: 4 a-LDS.64 + 8 w-LDS.64 + 32 fma.rn.f32x2 (covers k and
//    k+1 in one instr; lo/hi = even/odd-k partials, summed in epilogue).
//    Banks: a rows shift 4 banks per tn (APAD=68); w lanes on even banks.
// ---------------------------------------------------------------------------
__global__ void __launch_bounds__(128, 4)
gemm_relu_res_kernel(const float* __restrict__ W,
                     const float* __restrict__ x,
                     float* __restrict__ out,
                     int n_nodes) {
    __shared__ float2 Wt2[D2 * D];             // Wt2[k2*64 + o] (16 KB)
    __shared__ float  As[TILE_NODES * APAD];   // agg tile (17.4 KB)

    // stage W transposed as float2: Wt2[k2][o]
    {
        const float2* W2 = (const float2*)W;   // W2[o*32 + k2], coalesced
        for (int i = threadIdx.x; i < D * D2; i += blockDim.x) {
            int o  = i >> 5;
            int k2 = i & 31;
            Wt2[k2 * D + o] = W2[i];
        }
    }

    int base = blockIdx.x * TILE_NODES;

    // cooperative coalesced load of agg tile: 1024 float4, 128 threads -> 8 ea
    {
        const float4* ag = &g_agg[(long)base * D4];
        int lim = (n_nodes - base) * D4;
        if (lim > TILE_NODES * D4) lim = TILE_NODES * D4;
        for (int i = threadIdx.x; i < TILE_NODES * D4; i += blockDim.x) {
            float4 v = (i < lim) ? ag[i] : make_float4(0.f, 0.f, 0.f, 0.f);
            int row = i >> 4;
            int k4  = i & 15;
            *(float4*)&As[row * APAD + k4 * 4] = v;   // 272B stride, aligned
        }
    }
    __syncthreads();

    int t  = threadIdx.x;
    int to = t & 7;
    int tn = t >> 3;       // 0..15

    unsigned long long acc[4][8];
#pragma unroll
    for (int i = 0; i < 4; i++)
#pragma unroll
        for (int j = 0; j < 8; j++) acc[i][j] = 0ull;   // {0.0f, 0.0f}

#pragma unroll 4
    for (int k2 = 0; k2 < D2; k2++) {
        unsigned long long a[4];
#pragma unroll
        for (int i = 0; i < 4; i++)
            a[i] = *(const unsigned long long*)
                       &As[(tn + 16 * i) * APAD + k2 * 2];   // 8B-aligned

        unsigned long long w[8];
#pragma unroll
        for (int j = 0; j < 8; j++)
            w[j] = *(const unsigned long long*)&Wt2[k2 * D + to + 8 * j];

#pragma unroll
        for (int i = 0; i < 4; i++)
#pragma unroll
            for (int j = 0; j < 8; j++)
                acc[i][j] = ffma2(a[i], w[j], acc[i][j]);
    }

    // epilogue: fold lo+hi halves, relu + residual (o = to + 8j, stride-8)
#pragma unroll
    for (int i = 0; i < 4; i++) {
        int n = base + tn + 16 * i;
        if (n < n_nodes) {
            const float* xr = &x[(long)n * D];
            float*       od = &out[(long)n * D];
#pragma unroll
            for (int j = 0; j < 8; j++) {
                float2 p = *(float2*)&acc[i][j];
                float h  = p.x + p.y;
                int o = to + 8 * j;
                od[o] = fmaxf(h, 0.f) + xr[o];
            }
        }
    }
}

// ---------------------------------------------------------------------------
// Launch
// ---------------------------------------------------------------------------
extern "C" void kernel_launch(void* const* d_in, const int* in_sizes, int n_in,
                              void* d_out, int out_size) {
    const float* x   = (const float*)d_in[0];
    const float* W   = (const float*)d_in[1];
    const int*   src = (const int*)d_in[2];
    const int*   dst = (const int*)d_in[3];
    float*       out = (float*)d_out;

    int n_nodes = in_sizes[0] / D;
    int n_edges = in_sizes[2];

    const float4* x4   = (const float4*)x;
    const int4*   src4 = (const int4*)src;
    const int4*   dst4 = (const int4*)dst;

    // 1) fill buckets (cursors arrive zeroed)
    {
        int work = (n_edges >> 2) + 4;
        int threads = 256;
        int blocks = (work + threads - 1) / threads;
        fill_kernel<<<blocks, threads>>>(src4, dst4, src, dst, n_edges);
    }
    // 2) gather + cursor reset
    {
        long total = (long)n_nodes * 16;
        int threads = 256;
        int blocks = (int)((total + threads - 1) / threads);
        gather_kernel<<<blocks, threads>>>(x4, n_nodes);
    }
    // 3) smem GEMM + ReLU + residual (packed FFMA2)
    {
        int blocks = (n_nodes + TILE_NODES - 1) / TILE_NODES;
        gemm_relu_res_kernel<<<blocks, 128>>>(W, x, out, n_nodes);
    }
}

// round 14
// speedup vs baseline: 1.2965x; 1.2829x over previous
#include <cuda_runtime.h>
#include <cstdint>

// ---------------------------------------------------------------------------
// GCN layer, padded-bucket CSR (known-good pipeline skeleton):
//   1. cursor[n] = 0                                         (zero)
//   2. slot[d*CAP + cursor[d]++] = s                         (fill)
//   3. agg[n] = sum_j x[slot[n*CAP+j]]                       (gather)
//   4. out = relu(agg @ W^T) + x      (smem GEMM, packed fma.rn.f32x2:
//      lo/hi halves accumulate even/odd-k partials, folded in epilogue)
// ---------------------------------------------------------------------------

#define D 64
#define D4 (D / 4)
#define D2 (D / 2)
#define MAX_NODES 50000
#define CAP 96
#define TILE_NODES 64
#define APAD 68   // row stride (floats): 272B, 16B-aligned; banks shift 4/row

// __device__ scratch (allocations forbidden)
__device__ int    g_cursor[MAX_NODES];
__device__ int    g_slot[MAX_NODES * CAP];      // 19.2 MB
__device__ float4 g_agg[MAX_NODES * D4];        // 12.8 MB

// packed dual FMA: {d.lo,d.hi} = {a.lo*b.lo+c.lo, a.hi*b.hi+c.hi}
__device__ __forceinline__ unsigned long long
ffma2(unsigned long long a, unsigned long long b, unsigned long long c) {
    unsigned long long d;
    asm("fma.rn.f32x2 %0, %1, %2, %3;" : "=l"(d) : "l"(a), "l"(b), "l"(c));
    return d;
}

// ---------------------------------------------------------------------------
// 1. zero cursors
// ---------------------------------------------------------------------------
__global__ void zero_cursor_kernel(int n_nodes) {
    int i = blockIdx.x * blockDim.x + threadIdx.x;
    if (i < n_nodes) g_cursor[i] = 0;
}

// ---------------------------------------------------------------------------
// 2. fill buckets (4 edges per thread via int4 loads)
// ---------------------------------------------------------------------------
__global__ void fill_kernel(const int4* __restrict__ src4,
                            const int4* __restrict__ dst4,
                            const int* __restrict__ src,
                            const int* __restrict__ dst,
                            int n_edges) {
    int t = blockIdx.x * blockDim.x + threadIdx.x;
    int n4 = n_edges >> 2;
    if (t < n4) {
        int4 s = src4[t];
        int4 d = dst4[t];
        int p0 = atomicAdd(&g_cursor[d.x], 1);
        int p1 = atomicAdd(&g_cursor[d.y], 1);
        int p2 = atomicAdd(&g_cursor[d.z], 1);
        int p3 = atomicAdd(&g_cursor[d.w], 1);
        if (p0 < CAP) g_slot[d.x * CAP + p0] = s.x;
        if (p1 < CAP) g_slot[d.y * CAP + p1] = s.y;
        if (p2 < CAP) g_slot[d.z * CAP + p2] = s.z;
        if (p3 < CAP) g_slot[d.w * CAP + p3] = s.w;
    }
    if (t < (n_edges & 3)) {
        int e = (n4 << 2) + t;
        int d = dst[e];
        int p = atomicAdd(&g_cursor[d], 1);
        if (p < CAP) g_slot[d * CAP + p] = src[e];
    }
}

// ---------------------------------------------------------------------------
// 3. gather: 16 threads (half-warp) per node. Indices loaded coalesced
//    then shuffle-broadcast; x rows read as coalesced 256B.
// ---------------------------------------------------------------------------
__global__ void gather_kernel(const float4* __restrict__ x4, int n_nodes) {
    int gid  = blockIdx.x * blockDim.x + threadIdx.x;
    int node = gid >> 4;
    int lane = gid & 15;
    if (node >= n_nodes) return;

    int cnt = g_cursor[node];
    if (cnt > CAP) cnt = CAP;

    const int* slots = &g_slot[node * CAP];
    unsigned mask = (threadIdx.x & 16) ? 0xFFFF0000u : 0x0000FFFFu;

    float4 acc = make_float4(0.f, 0.f, 0.f, 0.f);

    for (int base = 0; base < cnt; base += 16) {
        int idx = slots[base + lane];
#pragma unroll
        for (int j = 0; j < 16; j++) {
            int s = __shfl_sync(mask, idx, j, 16);
            if (base + j < cnt) {
                float4 v = x4[(long)s * D4 + lane];
                acc.x += v.x; acc.y += v.y; acc.z += v.z; acc.w += v.w;
            }
        }
    }
    g_agg[(long)node * D4 + lane] = acc;
}

// ---------------------------------------------------------------------------
// 4. smem GEMM + ReLU + residual with packed FFMA2.
//    Block: 128 threads, 64 nodes. Thread (tn = t>>3 in 0..15, to = t&7):
//      nodes {tn + 16i : i<4} x outputs {to + 8j : j<8}.
//    Per k2-step: 4 a-LDS.64 + 8 w-LDS.64 + 32 fma.rn.f32x2.
//    Banks: a rows shift 4 banks per tn (APAD=68); w lanes on even banks.
//    Regs ~108 (acc 64 + a 8 + w 16 + misc) -> launch_bounds(128,4).
// ---------------------------------------------------------------------------
__global__ void __launch_bounds__(128, 4)
gemm_relu_res_kernel(const float* __restrict__ W,
                     const float* __restrict__ x,
                     float* __restrict__ out,
                     int n_nodes) {
    __shared__ float2 Wt2[D2 * D];             // Wt2[k2*64 + o] (16 KB)
    __shared__ float  As[TILE_NODES * APAD];   // agg tile (17.4 KB)

    // stage W transposed as float2: Wt2[k2][o]
    {
        const float2* W2 = (const float2*)W;   // W2[o*32 + k2], coalesced
        for (int i = threadIdx.x; i < D * D2; i += blockDim.x) {
            int o  = i >> 5;
            int k2 = i & 31;
            Wt2[k2 * D + o] = W2[i];
        }
    }

    int base = blockIdx.x * TILE_NODES;

    // cooperative coalesced load of agg tile: 1024 float4, 128 threads -> 8 ea
    {
        const float4* ag = &g_agg[(long)base * D4];
        int lim = (n_nodes - base) * D4;
        if (lim > TILE_NODES * D4) lim = TILE_NODES * D4;
        for (int i = threadIdx.x; i < TILE_NODES * D4; i += blockDim.x) {
            float4 v = (i < lim) ? ag[i] : make_float4(0.f, 0.f, 0.f, 0.f);
            int row = i >> 4;
            int k4  = i & 15;
            *(float4*)&As[row * APAD + k4 * 4] = v;   // 272B stride, aligned
        }
    }
    __syncthreads();

    int t  = threadIdx.x;
    int to = t & 7;
    int tn = t >> 3;       // 0..15

    unsigned long long acc[4][8];
#pragma unroll
    for (int i = 0; i < 4; i++)
#pragma unroll
        for (int j = 0; j < 8; j++) acc[i][j] = 0ull;   // {0.0f, 0.0f}

#pragma unroll 4
    for (int k2 = 0; k2 < D2; k2++) {
        unsigned long long a[4];
#pragma unroll
        for (int i = 0; i < 4; i++)
            a[i] = *(const unsigned long long*)
                       &As[(tn + 16 * i) * APAD + k2 * 2];   // 8B-aligned

        unsigned long long w[8];
#pragma unroll
        for (int j = 0; j < 8; j++)
            w[j] = *(const unsigned long long*)&Wt2[k2 * D + to + 8 * j];

#pragma unroll
        for (int i = 0; i < 4; i++)
#pragma unroll
            for (int j = 0; j < 8; j++)
                acc[i][j] = ffma2(a[i], w[j], acc[i][j]);
    }

    // epilogue: fold lo+hi halves, relu + residual (o = to + 8j, stride-8)
#pragma unroll
    for (int i = 0; i < 4; i++) {
        int n = base + tn + 16 * i;
        if (n < n_nodes) {
            const float* xr = &x[(long)n * D];
            float*       od = &out[(long)n * D];
#pragma unroll
            for (int j = 0; j < 8; j++) {
                float2 p = *(float2*)&acc[i][j];
                float h  = p.x + p.y;
                int o = to + 8 * j;
                od[o] = fmaxf(h, 0.f) + xr[o];
            }
        }
    }
}

// ---------------------------------------------------------------------------
// Launch
// ---------------------------------------------------------------------------
extern "C" void kernel_launch(void* const* d_in, const int* in_sizes, int n_in,
                              void* d_out, int out_size) {
    const float* x   = (const float*)d_in[0];
    const float* W   = (const float*)d_in[1];
    const int*   src = (const int*)d_in[2];
    const int*   dst = (const int*)d_in[3];
    float*       out = (float*)d_out;

    int n_nodes = in_sizes[0] / D;
    int n_edges = in_sizes[2];

    const float4* x4   = (const float4*)x;
    const int4*   src4 = (const int4*)src;
    const int4*   dst4 = (const int4*)dst;

    // 1) zero cursors
    {
        int threads = 256;
        int blocks = (n_nodes + threads - 1) / threads;
        zero_cursor_kernel<<<blocks, threads>>>(n_nodes);
    }
    // 2) fill buckets
    {
        int work = (n_edges >> 2) + 4;
        int threads = 256;
        int blocks = (work + threads - 1) / threads;
        fill_kernel<<<blocks, threads>>>(src4, dst4, src, dst, n_edges);
    }
    // 3) gather
    {
        long total = (long)n_nodes * 16;
        int threads = 256;
        int blocks = (int)((total + threads - 1) / threads);
        gather_kernel<<<blocks, threads>>>(x4, n_nodes);
    }
    // 4) smem GEMM + ReLU + residual (packed FFMA2)
    {
        int blocks = (n_nodes + TILE_NODES - 1) / TILE_NODES;
        gemm_relu_res_kernel<<<blocks, 128>>>(W, x, out, n_nodes);
    }
}

// round 15
// speedup vs baseline: 1.3621x; 1.0506x over previous
#include <cuda_runtime.h>
#include <cstdint>

// ---------------------------------------------------------------------------
// GCN layer, padded-bucket CSR (R6 skeleton, fill MLP doubled):
//   1. cursor[n] = 0                                         (zero)
//   2. slot[d*CAP + cursor[d]++] = s                         (fill, 8 edges/thr)
//   3. agg[n] = sum_j x[slot[n*CAP+j]]                       (gather)
//   4. out = relu(agg @ W^T) + x      (register-tiled GEMM, 4 nodes x 8 outs)
// ---------------------------------------------------------------------------

#define D 64
#define D4 (D / 4)
#define MAX_NODES 50000
#define CAP 96
#define TILE_NODES 128

// __device__ scratch (allocations forbidden)
__device__ int    g_cursor[MAX_NODES];
__device__ int    g_slot[MAX_NODES * CAP];      // 19.2 MB
__device__ float4 g_agg[MAX_NODES * D4];        // 12.8 MB

// ---------------------------------------------------------------------------
// 1. zero cursors
// ---------------------------------------------------------------------------
__global__ void zero_cursor_kernel(int n_nodes) {
    int i = blockIdx.x * blockDim.x + threadIdx.x;
    if (i < n_nodes) g_cursor[i] = 0;
}

// ---------------------------------------------------------------------------
// 2. fill buckets: 8 edges per thread (2x int4). All 8 atomicAdds are
//    independent and issue before the dependent stores -> MLP 8 per thread,
//    doubling in-flight atomics vs 4/thread (fill is ATOMG-latency-bound).
// ---------------------------------------------------------------------------
__global__ void fill_kernel(const int4* __restrict__ src4,
                            const int4* __restrict__ dst4,
                            const int* __restrict__ src,
                            const int* __restrict__ dst,
                            int n_edges) {
    int t = blockIdx.x * blockDim.x + threadIdx.x;
    int n8 = n_edges >> 3;
    if (t < n8) {
        int4 sa = src4[2 * t];
        int4 sb = src4[2 * t + 1];
        int4 da = dst4[2 * t];
        int4 db = dst4[2 * t + 1];
        int p0 = atomicAdd(&g_cursor[da.x], 1);
        int p1 = atomicAdd(&g_cursor[da.y], 1);
        int p2 = atomicAdd(&g_cursor[da.z], 1);
        int p3 = atomicAdd(&g_cursor[da.w], 1);
        int p4 = atomicAdd(&g_cursor[db.x], 1);
        int p5 = atomicAdd(&g_cursor[db.y], 1);
        int p6 = atomicAdd(&g_cursor[db.z], 1);
        int p7 = atomicAdd(&g_cursor[db.w], 1);
        if (p0 < CAP) g_slot[da.x * CAP + p0] = sa.x;
        if (p1 < CAP) g_slot[da.y * CAP + p1] = sa.y;
        if (p2 < CAP) g_slot[da.z * CAP + p2] = sa.z;
        if (p3 < CAP) g_slot[da.w * CAP + p3] = sa.w;
        if (p4 < CAP) g_slot[db.x * CAP + p4] = sb.x;
        if (p5 < CAP) g_slot[db.y * CAP + p5] = sb.y;
        if (p6 < CAP) g_slot[db.z * CAP + p6] = sb.z;
        if (p7 < CAP) g_slot[db.w * CAP + p7] = sb.w;
    }
    // tail: n_edges % 8 edges, one per thread
    if (t < (n_edges & 7)) {
        int e = (n8 << 3) + t;
        int d = dst[e];
        int p = atomicAdd(&g_cursor[d], 1);
        if (p < CAP) g_slot[d * CAP + p] = src[e];
    }
}

// ---------------------------------------------------------------------------
// 3. gather: 16 threads (half-warp) per node. Indices loaded coalesced
//    then shuffle-broadcast; x rows read as coalesced 256B.
// ---------------------------------------------------------------------------
__global__ void gather_kernel(const float4* __restrict__ x4, int n_nodes) {
    int gid  = blockIdx.x * blockDim.x + threadIdx.x;
    int node = gid >> 4;
    int lane = gid & 15;
    if (node >= n_nodes) return;

    int cnt = g_cursor[node];
    if (cnt > CAP) cnt = CAP;

    const int* slots = &g_slot[node * CAP];
    unsigned mask = (threadIdx.x & 16) ? 0xFFFF0000u : 0x0000FFFFu;

    float4 acc = make_float4(0.f, 0.f, 0.f, 0.f);

    for (int base = 0; base < cnt; base += 16) {
        int idx = slots[base + lane];
#pragma unroll
        for (int j = 0; j < 16; j++) {
            int s = __shfl_sync(mask, idx, j, 16);
            if (base + j < cnt) {
                float4 v = x4[(long)s * D4 + lane];
                acc.x += v.x; acc.y += v.y; acc.z += v.z; acc.w += v.w;
            }
        }
    }
    g_agg[(long)node * D4 + lane] = acc;
}

// ---------------------------------------------------------------------------
// 4. register-tiled GEMM + ReLU + residual (R6 verbatim — best measured).
//    Block: 256 threads, 128 nodes. Thread (tn = t>>3, to = t&7):
//    nodes {base+tn+32i : i<4} x outputs {to+8j : j<8}.
// ---------------------------------------------------------------------------
__global__ void __launch_bounds__(256)
gemm_relu_res_kernel(const float* __restrict__ W,
                     const float* __restrict__ x,
                     float* __restrict__ out,
                     int n_nodes) {
    __shared__ float4 Wt[D4 * D];   // Wt[k4*64 + o] = W[o][4k4..4k4+3]

    const float4* W4 = (const float4*)W;    // W4[o*16 + k4], coalesced read
    for (int i = threadIdx.x; i < D * D4; i += blockDim.x) {
        int o  = i >> 4;
        int k4 = i & 15;
        Wt[k4 * D + o] = W4[i];
    }
    __syncthreads();

    int t    = threadIdx.x;
    int to   = t & 7;      // output group
    int tn   = t >> 3;     // node group 0..31
    int base = blockIdx.x * TILE_NODES;

    int node[4];
#pragma unroll
    for (int i = 0; i < 4; i++) {
        int n = base + tn + 32 * i;
        node[i] = (n < n_nodes) ? n : (n_nodes - 1);   // clamp: safe LDG
    }

    float acc[4][8];
#pragma unroll
    for (int i = 0; i < 4; i++)
#pragma unroll
        for (int j = 0; j < 8; j++) acc[i][j] = 0.f;

#pragma unroll
    for (int k4 = 0; k4 < D4; k4++) {
        float4 a[4];
#pragma unroll
        for (int i = 0; i < 4; i++) a[i] = g_agg[node[i] * D4 + k4];

        float4 w[8];
#pragma unroll
        for (int j = 0; j < 8; j++) w[j] = Wt[k4 * D + to + 8 * j];

#pragma unroll
        for (int i = 0; i < 4; i++) {
#pragma unroll
            for (int j = 0; j < 8; j++) {
                acc[i][j] = fmaf(a[i].x, w[j].x, acc[i][j]);
                acc[i][j] = fmaf(a[i].y, w[j].y, acc[i][j]);
                acc[i][j] = fmaf(a[i].z, w[j].z, acc[i][j]);
                acc[i][j] = fmaf(a[i].w, w[j].w, acc[i][j]);
            }
        }
    }

    // epilogue: relu + residual, scalar stores (o = to + 8j, stride-8)
#pragma unroll
    for (int i = 0; i < 4; i++) {
        int n = base + tn + 32 * i;
        if (n < n_nodes) {
            const float* xr = &x[(long)n * D];
            float*       od = &out[(long)n * D];
#pragma unroll
            for (int j = 0; j < 8; j++) {
                int o = to + 8 * j;
                od[o] = fmaxf(acc[i][j], 0.f) + xr[o];
            }
        }
    }
}

// ---------------------------------------------------------------------------
// Launch
// ---------------------------------------------------------------------------
extern "C" void kernel_launch(void* const* d_in, const int* in_sizes, int n_in,
                              void* d_out, int out_size) {
    const float* x   = (const float*)d_in[0];
    const float* W   = (const float*)d_in[1];
    const int*   src = (const int*)d_in[2];
    const int*   dst = (const int*)d_in[3];
    float*       out = (float*)d_out;

    int n_nodes = in_sizes[0] / D;
    int n_edges = in_sizes[2];

    const float4* x4   = (const float4*)x;
    const int4*   src4 = (const int4*)src;
    const int4*   dst4 = (const int4*)dst;

    // 1) zero cursors
    {
        int threads = 256;
        int blocks = (n_nodes + threads - 1) / threads;
        zero_cursor_kernel<<<blocks, threads>>>(n_nodes);
    }
    // 2) fill buckets (8 edges/thread)
    {
        int work = (n_edges >> 3) + 8;
        int threads = 256;
        int blocks = (work + threads - 1) / threads;
        fill_kernel<<<blocks, threads>>>(src4, dst4, src, dst, n_edges);
    }
    // 3) gather
    {
        long total = (long)n_nodes * 16;
        int threads = 256;
        int blocks = (int)((total + threads - 1) / threads);
        gather_kernel<<<blocks, threads>>>(x4, n_nodes);
    }
    // 4) register-tiled GEMM + ReLU + residual
    {
        int blocks = (n_nodes + TILE_NODES - 1) / TILE_NODES;
        gemm_relu_res_kernel<<<blocks, 256>>>(W, x, out, n_nodes);
    }
}

// round 16
// speedup vs baseline: 1.6060x; 1.1791x over previous
#include <cuda_runtime.h>
#include <cstdint>

// ---------------------------------------------------------------------------
// GCN layer, reordered algebra + tf32 tensor-core GEMM:
//   1. y = x @ W^T  (tf32 mma.sync, fp32 accum); also zeroes cursors
//   2. slot[d*CAP + cursor[d]++] = s                 (fill, 8 edges/thread)
//   3. out[n] = relu(sum_j y[slot[n*CAP+j]]) + x[n]  (gather + fused epilogue)
// Uses relu(sum x[s] @ W^T) == relu(sum (x@W^T)[s]) to hoist the GEMM off the
// critical edge path and kill the agg round-trip.
// ---------------------------------------------------------------------------

#define D 64
#define D4 (D / 4)
#define MAX_NODES 50000
#define CAP 96
#define TILE_NODES 64     // nodes per gemm block (4 warps x 16-row strips)
#define APAD 68           // padded row stride: banks shift 4/row, 16B-aligned

// __device__ scratch (allocations forbidden)
__device__ int   g_cursor[MAX_NODES];
__device__ int   g_slot[MAX_NODES * CAP];     // 19.2 MB
__device__ float g_y[MAX_NODES * D];          // 12.8 MB

__device__ __forceinline__ unsigned f2tf32(float f) {
    unsigned r;
    asm("cvt.rna.tf32.f32 %0, %1;" : "=r"(r) : "f"(f));
    return r;
}

// ---------------------------------------------------------------------------
// 1. GEMM: y = x @ W^T via tf32 m16n8k8 mma.sync. Block: 128 thr, 64 nodes.
//    Warp strip = 16 nodes x 64 outs: preload 8 k-tile A-frags (32 regs),
//    loop 8 n-tiles x 8 k-tiles of mma. Also zeroes cursors (runs first).
// ---------------------------------------------------------------------------
__global__ void __launch_bounds__(128, 6)
gemm_y_kernel(const float* __restrict__ x,
              const float* __restrict__ W,
              int n_nodes) {
    __shared__ unsigned As[TILE_NODES * APAD];  // x tile, tf32 bits (17.4 KB)
    __shared__ unsigned Ws[D * APAD];           // W, tf32 bits       (17.4 KB)

    int tid  = threadIdx.x;
    int base = blockIdx.x * TILE_NODES;

    // fold in cursor zeroing (gemm is the first kernel in the pipeline)
    {
        int gz = blockIdx.x * blockDim.x + tid;
        if (gz < n_nodes) g_cursor[gz] = 0;
    }

    // stage W[o][k] -> Ws (tf32)
    for (int i = tid; i < D * D; i += 128) {
        int o = i >> 6, k = i & 63;
        Ws[o * APAD + k] = f2tf32(W[i]);
    }
    // stage x tile -> As (tf32), zero-pad past n_nodes
    {
        int lim = (n_nodes - base) * D;
        if (lim > TILE_NODES * D) lim = TILE_NODES * D;
        for (int i = tid; i < TILE_NODES * D; i += 128) {
            float v = (i < lim) ? x[(long)base * D + i] : 0.f;
            int r = i >> 6, k = i & 63;
            As[r * APAD + k] = f2tf32(v);
        }
    }
    __syncthreads();

    int warp = tid >> 5, lane = tid & 31;
    int gi = lane >> 2, ti = lane & 3;
    int row0 = warp * 16 + gi;              // strip-local row

    // preload A fragments for all 8 k-tiles
    unsigned a[8][4];
#pragma unroll
    for (int kt = 0; kt < 8; kt++) {
        a[kt][0] = As[(row0)     * APAD + kt * 8 + ti];
        a[kt][1] = As[(row0 + 8) * APAD + kt * 8 + ti];
        a[kt][2] = As[(row0)     * APAD + kt * 8 + ti + 4];
        a[kt][3] = As[(row0 + 8) * APAD + kt * 8 + ti + 4];
    }

    int n0 = base + row0;
    int n1 = n0 + 8;

#pragma unroll
    for (int nt = 0; nt < 8; nt++) {
        float d0 = 0.f, d1 = 0.f, d2 = 0.f, d3 = 0.f;
#pragma unroll
        for (int kt = 0; kt < 8; kt++) {
            unsigned b0 = Ws[(nt * 8 + gi) * APAD + kt * 8 + ti];
            unsigned b1 = Ws[(nt * 8 + gi) * APAD + kt * 8 + ti + 4];
            asm("mma.sync.aligned.m16n8k8.row.col.f32.tf32.tf32.f32 "
                "{%0,%1,%2,%3},{%4,%5,%6,%7},{%8,%9},{%0,%1,%2,%3};"
                : "+f"(d0), "+f"(d1), "+f"(d2), "+f"(d3)
                : "r"(a[kt][0]), "r"(a[kt][1]), "r"(a[kt][2]), "r"(a[kt][3]),
                  "r"(b0), "r"(b1));
        }
        int c = nt * 8 + ti * 2;            // even -> 8B-aligned float2
        if (n0 < n_nodes) *(float2*)&g_y[(long)n0 * D + c] = make_float2(d0, d1);
        if (n1 < n_nodes) *(float2*)&g_y[(long)n1 * D + c] = make_float2(d2, d3);
    }
}

// ---------------------------------------------------------------------------
// 2. fill buckets: 8 edges per thread (2x int4), independent atomics
// ---------------------------------------------------------------------------
__global__ void fill_kernel(const int4* __restrict__ src4,
                            const int4* __restrict__ dst4,
                            const int* __restrict__ src,
                            const int* __restrict__ dst,
                            int n_edges) {
    int t = blockIdx.x * blockDim.x + threadIdx.x;
    int n8 = n_edges >> 3;
    if (t < n8) {
        int4 sa = src4[2 * t];
        int4 sb = src4[2 * t + 1];
        int4 da = dst4[2 * t];
        int4 db = dst4[2 * t + 1];
        int p0 = atomicAdd(&g_cursor[da.x], 1);
        int p1 = atomicAdd(&g_cursor[da.y], 1);
        int p2 = atomicAdd(&g_cursor[da.z], 1);
        int p3 = atomicAdd(&g_cursor[da.w], 1);
        int p4 = atomicAdd(&g_cursor[db.x], 1);
        int p5 = atomicAdd(&g_cursor[db.y], 1);
        int p6 = atomicAdd(&g_cursor[db.z], 1);
        int p7 = atomicAdd(&g_cursor[db.w], 1);
        if (p0 < CAP) g_slot[da.x * CAP + p0] = sa.x;
        if (p1 < CAP) g_slot[da.y * CAP + p1] = sa.y;
        if (p2 < CAP) g_slot[da.z * CAP + p2] = sa.z;
        if (p3 < CAP) g_slot[da.w * CAP + p3] = sa.w;
        if (p4 < CAP) g_slot[db.x * CAP + p4] = sb.x;
        if (p5 < CAP) g_slot[db.y * CAP + p5] = sb.y;
        if (p6 < CAP) g_slot[db.z * CAP + p6] = sb.z;
        if (p7 < CAP) g_slot[db.w * CAP + p7] = sb.w;
    }
    if (t < (n_edges & 7)) {
        int e = (n8 << 3) + t;
        int d = dst[e];
        int p = atomicAdd(&g_cursor[d], 1);
        if (p < CAP) g_slot[d * CAP + p] = src[e];
    }
}

// ---------------------------------------------------------------------------
// 3. gather + fused relu/residual: 16 threads (half-warp) per node.
//    Sums y rows (coalesced 256B reads), then out = relu(sum) + x.
// ---------------------------------------------------------------------------
__global__ void gather_kernel(const float4* __restrict__ x4,
                              float4* __restrict__ out4,
                              int n_nodes) {
    int gid  = blockIdx.x * blockDim.x + threadIdx.x;
    int node = gid >> 4;
    int lane = gid & 15;
    if (node >= n_nodes) return;

    int cnt = g_cursor[node];
    if (cnt > CAP) cnt = CAP;

    const int* slots = &g_slot[node * CAP];
    const float4* y4 = (const float4*)g_y;
    unsigned mask = (threadIdx.x & 16) ? 0xFFFF0000u : 0x0000FFFFu;

    float4 acc = make_float4(0.f, 0.f, 0.f, 0.f);

    for (int base = 0; base < cnt; base += 16) {
        int idx = slots[base + lane];
#pragma unroll
        for (int j = 0; j < 16; j++) {
            int s = __shfl_sync(mask, idx, j, 16);
            if (base + j < cnt) {
                float4 v = y4[(long)s * D4 + lane];
                acc.x += v.x; acc.y += v.y; acc.z += v.z; acc.w += v.w;
            }
        }
    }

    float4 xr = x4[(long)node * D4 + lane];
    float4 r;
    r.x = fmaxf(acc.x, 0.f) + xr.x;
    r.y = fmaxf(acc.y, 0.f) + xr.y;
    r.z = fmaxf(acc.z, 0.f) + xr.z;
    r.w = fmaxf(acc.w, 0.f) + xr.w;
    out4[(long)node * D4 + lane] = r;
}

// ---------------------------------------------------------------------------
// Launch: gemm_y (zeros cursors) -> fill -> gather
// ---------------------------------------------------------------------------
extern "C" void kernel_launch(void* const* d_in, const int* in_sizes, int n_in,
                              void* d_out, int out_size) {
    const float* x   = (const float*)d_in[0];
    const float* W   = (const float*)d_in[1];
    const int*   src = (const int*)d_in[2];
    const int*   dst = (const int*)d_in[3];
    float*       out = (float*)d_out;

    int n_nodes = in_sizes[0] / D;
    int n_edges = in_sizes[2];

    const float4* x4   = (const float4*)x;
    float4*       out4 = (float4*)out;
    const int4*   src4 = (const int4*)src;
    const int4*   dst4 = (const int4*)dst;

    // 1) y = x @ W^T (also zeroes cursors)
    {
        int blocks = (n_nodes + TILE_NODES - 1) / TILE_NODES;
        gemm_y_kernel<<<blocks, 128>>>(x, W, n_nodes);
    }
    // 2) fill buckets
    {
        int work = (n_edges >> 3) + 8;
        int threads = 256;
        int blocks = (work + threads - 1) / threads;
        fill_kernel<<<blocks, threads>>>(src4, dst4, src, dst, n_edges);
    }
    // 3) gather + relu + residual
    {
        long total = (long)n_nodes * 16;
        int threads = 256;
        int blocks = (int)((total + threads - 1) / threads);
        gather_kernel<<<blocks, threads>>>(x4, out4, n_nodes);
    }
}

// round 17
// speedup vs baseline: 1.6072x; 1.0007x over previous
#include <cuda_runtime.h>
#include <cstdint>

// ---------------------------------------------------------------------------
// GCN layer, reordered algebra + tf32 tensor-core GEMM:
//   0. prep: zero cursors; convert W -> tf32 image          (prep)
//   1. y = x @ W^T  (tf32 mma.sync, fp32 accum)             (gemm_y)
//   2. slot[d*CAP + cursor[d]++] = s                        (fill)
//   3. out[n] = relu(sum_j y[slot[n*CAP+j]]) + x[n]         (gather+epilogue)
// relu(sum x[s] @ W^T) == relu(sum (x@W^T)[s]) hoists the GEMM off the edge
// path; no agg round-trip.
// ---------------------------------------------------------------------------

#define D 64
#define D4 (D / 4)
#define MAX_NODES 50000
#define CAP 96
#define TILE_NODES 64     // nodes per gemm block (4 warps x 16-row strips)
#define APAD 68           // padded row stride: banks shift 4/row, 16B-aligned

// __device__ scratch (allocations forbidden)
__device__ int      g_cursor[MAX_NODES];
__device__ int      g_slot[MAX_NODES * CAP];     // 19.2 MB
__device__ float    g_y[MAX_NODES * D];          // 12.8 MB
__device__ unsigned g_wt[D * D];                 // W as tf32 bits (16 KB)

__device__ __forceinline__ unsigned f2tf32(float f) {
    unsigned r;
    asm("cvt.rna.tf32.f32 %0, %1;" : "=r"(r) : "f"(f));
    return r;
}

// ---------------------------------------------------------------------------
// 0. prep: zero cursors; first 4096 threads also convert W to tf32 bits
// ---------------------------------------------------------------------------
__global__ void prep_kernel(const float* __restrict__ W, int n_nodes) {
    int i = blockIdx.x * blockDim.x + threadIdx.x;
    if (i < n_nodes) g_cursor[i] = 0;
    if (i < D * D)   g_wt[i] = f2tf32(W[i]);
}

// ---------------------------------------------------------------------------
// 1. GEMM: y = x @ W^T via tf32 m16n8k8 mma.sync. Block: 128 thr, 64 nodes.
//    Staging vectorized 4x: Ws copied as uint4 from the pre-converted tf32
//    image; As loaded as float4 + 4 cvt. Warp strip = 16 nodes x 64 outs.
// ---------------------------------------------------------------------------
__global__ void __launch_bounds__(128, 6)
gemm_y_kernel(const float* __restrict__ x, int n_nodes) {
    __shared__ unsigned As[TILE_NODES * APAD];  // x tile, tf32 bits (17.4 KB)
    __shared__ unsigned Ws[D * APAD];           // W, tf32 bits       (17.4 KB)

    int tid  = threadIdx.x;
    int base = blockIdx.x * TILE_NODES;

    // stage W image -> Ws (uint4 copy: 4096/4 = 1024 vec, 128 thr -> 8 iters)
    {
        const uint4* w4 = (const uint4*)g_wt;
        for (int v = tid; v < (D * D) / 4; v += 128) {
            int i = v * 4;
            int o = i >> 6, k = i & 63;
            *(uint4*)&Ws[o * APAD + k] = w4[v];   // k%4==0 -> 16B aligned
        }
    }
    // stage x tile -> As (float4 + cvt x4: 8 iters)
    {
        const float4* xf4 = (const float4*)(x + (long)base * D);
        int lim = (n_nodes - base) * 16;          // available float4 count
        if (lim > TILE_NODES * 16) lim = TILE_NODES * 16;
        for (int v = tid; v < TILE_NODES * 16; v += 128) {
            float4 f = (v < lim) ? xf4[v] : make_float4(0.f, 0.f, 0.f, 0.f);
            uint4 u = make_uint4(f2tf32(f.x), f2tf32(f.y),
                                 f2tf32(f.z), f2tf32(f.w));
            int i = v * 4;
            int r = i >> 6, k = i & 63;
            *(uint4*)&As[r * APAD + k] = u;
        }
    }
    __syncthreads();

    int warp = tid >> 5, lane = tid & 31;
    int gi = lane >> 2, ti = lane & 3;
    int row0 = warp * 16 + gi;              // strip-local row

    // preload A fragments for all 8 k-tiles (32 regs)
    unsigned a[8][4];
#pragma unroll
    for (int kt = 0; kt < 8; kt++) {
        a[kt][0] = As[(row0)     * APAD + kt * 8 + ti];
        a[kt][1] = As[(row0 + 8) * APAD + kt * 8 + ti];
        a[kt][2] = As[(row0)     * APAD + kt * 8 + ti + 4];
        a[kt][3] = As[(row0 + 8) * APAD + kt * 8 + ti + 4];
    }

    int n0 = base + row0;
    int n1 = n0 + 8;

#pragma unroll
    for (int nt = 0; nt < 8; nt++) {
        float d0 = 0.f, d1 = 0.f, d2 = 0.f, d3 = 0.f;
#pragma unroll
        for (int kt = 0; kt < 8; kt++) {
            unsigned b0 = Ws[(nt * 8 + gi) * APAD + kt * 8 + ti];
            unsigned b1 = Ws[(nt * 8 + gi) * APAD + kt * 8 + ti + 4];
            asm("mma.sync.aligned.m16n8k8.row.col.f32.tf32.tf32.f32 "
                "{%0,%1,%2,%3},{%4,%5,%6,%7},{%8,%9},{%0,%1,%2,%3};"
                : "+f"(d0), "+f"(d1), "+f"(d2), "+f"(d3)
                : "r"(a[kt][0]), "r"(a[kt][1]), "r"(a[kt][2]), "r"(a[kt][3]),
                  "r"(b0), "r"(b1));
        }
        int c = nt * 8 + ti * 2;            // even -> 8B-aligned float2
        if (n0 < n_nodes) *(float2*)&g_y[(long)n0 * D + c] = make_float2(d0, d1);
        if (n1 < n_nodes) *(float2*)&g_y[(long)n1 * D + c] = make_float2(d2, d3);
    }
}

// ---------------------------------------------------------------------------
// 2. fill buckets: 8 edges per thread (2x int4), independent atomics
// ---------------------------------------------------------------------------
__global__ void fill_kernel(const int4* __restrict__ src4,
                            const int4* __restrict__ dst4,
                            const int* __restrict__ src,
                            const int* __restrict__ dst,
                            int n_edges) {
    int t = blockIdx.x * blockDim.x + threadIdx.x;
    int n8 = n_edges >> 3;
    if (t < n8) {
        int4 sa = src4[2 * t];
        int4 sb = src4[2 * t + 1];
        int4 da = dst4[2 * t];
        int4 db = dst4[2 * t + 1];
        int p0 = atomicAdd(&g_cursor[da.x], 1);
        int p1 = atomicAdd(&g_cursor[da.y], 1);
        int p2 = atomicAdd(&g_cursor[da.z], 1);
        int p3 = atomicAdd(&g_cursor[da.w], 1);
        int p4 = atomicAdd(&g_cursor[db.x], 1);
        int p5 = atomicAdd(&g_cursor[db.y], 1);
        int p6 = atomicAdd(&g_cursor[db.z], 1);
        int p7 = atomicAdd(&g_cursor[db.w], 1);
        if (p0 < CAP) g_slot[da.x * CAP + p0] = sa.x;
        if (p1 < CAP) g_slot[da.y * CAP + p1] = sa.y;
        if (p2 < CAP) g_slot[da.z * CAP + p2] = sa.z;
        if (p3 < CAP) g_slot[da.w * CAP + p3] = sa.w;
        if (p4 < CAP) g_slot[db.x * CAP + p4] = sb.x;
        if (p5 < CAP) g_slot[db.y * CAP + p5] = sb.y;
        if (p6 < CAP) g_slot[db.z * CAP + p6] = sb.z;
        if (p7 < CAP) g_slot[db.w * CAP + p7] = sb.w;
    }
    if (t < (n_edges & 7)) {
        int e = (n8 << 3) + t;
        int d = dst[e];
        int p = atomicAdd(&g_cursor[d], 1);
        if (p < CAP) g_slot[d * CAP + p] = src[e];
    }
}

// ---------------------------------------------------------------------------
// 3. gather + fused relu/residual: 16 threads (half-warp) per node.
// ---------------------------------------------------------------------------
__global__ void gather_kernel(const float4* __restrict__ x4,
                              float4* __restrict__ out4,
                              int n_nodes) {
    int gid  = blockIdx.x * blockDim.x + threadIdx.x;
    int node = gid >> 4;
    int lane = gid & 15;
    if (node >= n_nodes) return;

    int cnt = g_cursor[node];
    if (cnt > CAP) cnt = CAP;

    const int* slots = &g_slot[node * CAP];
    const float4* y4 = (const float4*)g_y;
    unsigned mask = (threadIdx.x & 16) ? 0xFFFF0000u : 0x0000FFFFu;

    float4 acc = make_float4(0.f, 0.f, 0.f, 0.f);

    for (int base = 0; base < cnt; base += 16) {
        int idx = slots[base + lane];
#pragma unroll
        for (int j = 0; j < 16; j++) {
            int s = __shfl_sync(mask, idx, j, 16);
            if (base + j < cnt) {
                float4 v = y4[(long)s * D4 + lane];
                acc.x += v.x; acc.y += v.y; acc.z += v.z; acc.w += v.w;
            }
        }
    }

    float4 xr = x4[(long)node * D4 + lane];
    float4 r;
    r.x = fmaxf(acc.x, 0.f) + xr.x;
    r.y = fmaxf(acc.y, 0.f) + xr.y;
    r.z = fmaxf(acc.z, 0.f) + xr.z;
    r.w = fmaxf(acc.w, 0.f) + xr.w;
    out4[(long)node * D4 + lane] = r;
}

// ---------------------------------------------------------------------------
// Launch: prep -> gemm_y -> fill -> gather
// ---------------------------------------------------------------------------
extern "C" void kernel_launch(void* const* d_in, const int* in_sizes, int n_in,
                              void* d_out, int out_size) {
    const float* x   = (const float*)d_in[0];
    const float* W   = (const float*)d_in[1];
    const int*   src = (const int*)d_in[2];
    const int*   dst = (const int*)d_in[3];
    float*       out = (float*)d_out;

    int n_nodes = in_sizes[0] / D;
    int n_edges = in_sizes[2];

    const float4* x4   = (const float4*)x;
    float4*       out4 = (float4*)out;
    const int4*   src4 = (const int4*)src;
    const int4*   dst4 = (const int4*)dst;

    // 0) prep: zero cursors + W -> tf32
    {
        int threads = 256;
        int blocks = (n_nodes + threads - 1) / threads;
        prep_kernel<<<blocks, threads>>>(W, n_nodes);
    }
    // 1) y = x @ W^T
    {
        int blocks = (n_nodes + TILE_NODES - 1) / TILE_NODES;
        gemm_y_kernel<<<blocks, 128>>>(x, n_nodes);
    }
    // 2) fill buckets
    {
        int work = (n_edges >> 3) + 8;
        int threads = 256;
        int blocks = (work + threads - 1) / threads;
        fill_kernel<<<blocks, threads>>>(src4, dst4, src, dst, n_edges);
    }
    // 3) gather + relu + residual
    {
        long total = (long)n_nodes * 16;
        int threads = 256;
        int blocks = (int)((total + threads - 1) / threads);
        gather_kernel<<<blocks, threads>>>(x4, out4, n_nodes);
    }
}